// round 1
// baseline (speedup 1.0000x reference)
#include <cuda_runtime.h>

#define TT 2048
#define DD 64
#define HH 64
#define NG 256   // 4*H gates

// Packed fp32x2 FMA (sm_100+): d = a*b + c on two packed floats.
__device__ __forceinline__ unsigned long long ffma2(unsigned long long a,
                                                    unsigned long long b,
                                                    unsigned long long c) {
    unsigned long long d;
    asm("fma.rn.f32x2 %0, %1, %2, %3;" : "=l"(d) : "l"(a), "l"(b), "l"(c));
    return d;
}

__device__ __forceinline__ float red2(unsigned long long v) {
    float lo, hi;
    asm("mov.b64 {%0, %1}, %2;" : "=f"(lo), "=f"(hi) : "l"(v));
    return lo + hi;
}

// 64-element dot: w in registers (16 x ulonglong2 = 64 packed floats),
// v in shared memory (read as LDS.128, broadcast -> conflict-free).
__device__ __forceinline__ float dot64(const ulonglong2* __restrict__ w,
                                       const ulonglong2* v) {
    unsigned long long a0 = 0ull, a1 = 0ull;
#pragma unroll
    for (int j = 0; j < 16; ++j) {
        ulonglong2 h2 = v[j];
        a0 = ffma2(w[j].x, h2.x, a0);
        a1 = ffma2(w[j].y, h2.y, a1);
    }
    return red2(a0) + red2(a1);
}

__device__ __forceinline__ float sigm(float v) {
    return __fdividef(1.f, 1.f + __expf(-v));
}
__device__ __forceinline__ float tanh_(float v) {
    // 1 - 2/(1+e^{2v}): saturates correctly at +-1 for large |v|
    return 1.f - __fdividef(2.f, 1.f + __expf(2.f * v));
}

__global__ void __launch_bounds__(256, 1)
lstm_fused(const float* __restrict__ x, const float* __restrict__ w_ih,
           const float* __restrict__ w_hh, const float* __restrict__ b_ih,
           const float* __restrict__ b_hh, const float* __restrict__ fc_w,
           const float* __restrict__ fc_b, float* __restrict__ out, int Tn)
{
    __shared__ __align__(16) float hsm[2][HH];       // h state, 2 batches
    __shared__ __align__(16) float xsm[2][2][DD];    // x double buffer [slot][batch][k]
    __shared__ __align__(16) float gbuf[2][NG];      // gate preactivations

    const int tid = threadIdx.x;
    const int g = tid;                 // gate index 0..255
    const int b0 = blockIdx.x * 2;     // 2 batches per block

    // Register-resident weight rows for this gate (packed f32x2 pairs)
    ulonglong2 whh[16], wih[16];
    {
        const ulonglong2* wp = (const ulonglong2*)(w_hh + g * HH);
        const ulonglong2* ip = (const ulonglong2*)(w_ih + g * DD);
#pragma unroll
        for (int j = 0; j < 16; ++j) { whh[j] = wp[j]; wih[j] = ip[j]; }
    }
    const float bias = b_ih[g] + b_hh[g];

    // init h=0, stage x[0], x[1]
    if (tid < 128) {
        ((float*)hsm)[tid] = 0.f;
        int bb = tid >> 6, k = tid & 63;
        xsm[0][bb][k] = x[((size_t)(b0 + bb) * Tn + 0) * DD + k];
        xsm[1][bb][k] = x[((size_t)(b0 + bb) * Tn + 1) * DD + k];
    }
    __syncthreads();

    // xg for t=0 (input projection + bias)
    float xg0 = bias + dot64(wih, (const ulonglong2*)xsm[0][0]);
    float xg1 = bias + dot64(wih, (const ulonglong2*)xsm[0][1]);

    // prefetch x[2] into registers (warp 7, 32 float4 = 2 batches x 16)
    float4 pre = make_float4(0.f, 0.f, 0.f, 0.f);
    if (tid >= 224) {
        int l = tid - 224, bb = l >> 4, k4 = l & 15;
        pre = *(const float4*)(x + ((size_t)(b0 + bb) * Tn + 2) * DD + k4 * 4);
    }

    float c = 0.f;  // cell state (only meaningful for tid < 128)

    for (int t = 0; t < Tn; ++t) {
        // ---- phase 1: all 256 threads compute gate preactivations for step t
        //      and the input projection for step t+1 ----
        float s0 = xg0 + dot64(whh, (const ulonglong2*)hsm[0]);
        float s1 = xg1 + dot64(whh, (const ulonglong2*)hsm[1]);
        gbuf[0][g] = s0;
        gbuf[1][g] = s1;
        float n0 = bias + dot64(wih, (const ulonglong2*)xsm[(t + 1) & 1][0]);
        float n1 = bias + dot64(wih, (const ulonglong2*)xsm[(t + 1) & 1][1]);
        __syncthreads();
        xg0 = n0; xg1 = n1;

        // ---- phase 2: 128 unit threads do elementwise LSTM update;
        //      warp 7 stages x[t+2] into SMEM and prefetches x[t+3] ----
        if (tid < 128) {
            int bb = tid >> 6, u = tid & 63;
            float gi = sigm(gbuf[bb][u]);
            float gf = sigm(gbuf[bb][64 + u]);
            float gg = tanh_(gbuf[bb][128 + u]);
            float go = sigm(gbuf[bb][192 + u]);
            c = gf * c + gi * gg;
            hsm[bb][u] = go * tanh_(c);
        } else if (tid >= 224) {
            int l = tid - 224, bb = l >> 4, k4 = l & 15;
            if (t + 2 < Tn)
                *(float4*)&xsm[t & 1][bb][k4 * 4] = pre;
            if (t + 3 < Tn)
                pre = *(const float4*)(x + ((size_t)(b0 + bb) * Tn + (t + 3)) * DD + k4 * 4);
        }
        __syncthreads();
    }

    // ---- final FC: out[b, o] = h_last . fc_w[o] + fc_b[o] ----
    if (tid < 16) {
        int bb = tid >> 3, o = tid & 7;
        float s = fc_b[o];
#pragma unroll
        for (int k = 0; k < HH; ++k) s += hsm[bb][k] * fc_w[o * HH + k];
        out[(b0 + bb) * 8 + o] = s;
    }
}

extern "C" void kernel_launch(void* const* d_in, const int* in_sizes, int n_in,
                              void* d_out, int out_size) {
    const float* x    = (const float*)d_in[0];
    const float* w_ih = (const float*)d_in[1];
    const float* w_hh = (const float*)d_in[2];
    const float* b_ih = (const float*)d_in[3];
    const float* b_hh = (const float*)d_in[4];
    const float* fc_w = (const float*)d_in[5];
    const float* fc_b = (const float*)d_in[6];
    float* out = (float*)d_out;

    int B = in_sizes[0] / (TT * DD);   // 256
    lstm_fused<<<B / 2, 256>>>(x, w_ih, w_hh, b_ih, b_hh, fc_w, fc_b, out, TT);
}